// round 11
// baseline (speedup 1.0000x reference)
#include <cuda_runtime.h>
#include <cuda_fp16.h>
#include <cstdint>
#include <cstddef>

// ---------------------------------------------------------------------------
// HolleyGAT: hetero 2-layer GATConv + projections.
// GEMMs on tensor cores (mma.sync tf32, fp32 accumulate), BM=64 (2 CTA/SM).
// Relation GEMM outputs stored fp16 to halve edge-gather traffic.
// Edge aggregation via per-dst CSR: warp per dst row, SINGLE fused pass
// (den & acc together), one vector reduction per row.
// All attention logit vectors per layer/node-type computed in one X pass.
// ---------------------------------------------------------------------------

#define CDIV(a,b) (((a)+(b)-1)/(b))

static const int MAX_NU  = 200000;
static const int MAX_NPR = 100000;
static const int MAX_NV  = 20000;

__device__ float g_xp [MAX_NPR*128];
__device__ float g_ou [(size_t)MAX_NU*128];
__device__ float g_op [MAX_NPR*128];
__device__ float g_ov [MAX_NV*128];
__device__ float g_xu2[(size_t)MAX_NU*128];
__device__ float g_xp2[MAX_NPR*128];
__device__ float g_hs [(size_t)MAX_NU*128];     // fp32 scratch (projections)
__device__ float g_hd [(size_t)MAX_NU*128];
__device__ __half g_hsh[(size_t)MAX_NU*128];    // fp16 h_src for aggregation
__device__ float g_albuf[(size_t)14*MAX_NU*4];  // logit slots (14 max/layer)
__device__ float g_vmat[12*2*512];
// CSR scratch (7 directions; node slots 740k, edge slots 3.6M)
__device__ int g_cnt[800000];
__device__ int g_rowptr[800000];
__device__ int g_cursor[800000];
__device__ int g_part[800000];
__device__ int g_bsum[7*256];
__device__ int g_srt[3600000];

// ---------------------------------------------------------------------------
__global__ void k_feat(const int* __restrict__ pt_id,
                       const float* __restrict__ x_num,
                       const float* __restrict__ pt_emb,
                       const float* __restrict__ fW,
                       const float* __restrict__ fb,
                       const float* __restrict__ pemb,
                       float* __restrict__ xp, int npr)
{
    int idx = blockIdx.x * blockDim.x + threadIdx.x;
    if (idx >= npr * 128) return;
    int row = idx >> 7, c = idx & 127;
    int t = pt_id[row];
    float acc = fb[c];
    const float* pe = pt_emb + (size_t)t * 32;
    #pragma unroll
    for (int k = 0; k < 32; k++) acc += pe[k] * fW[k*128 + c];
    const float* xn = x_num + (size_t)row * 3;
    #pragma unroll
    for (int k = 0; k < 3; k++) acc += xn[k] * fW[(32+k)*128 + c];
    acc = fmaxf(acc, 0.f);
    xp[idx] = pemb[idx] + acc;
}

// ---------------------------------------------------------------------------
// tf32 tensor-core GEMM, BM=64 rows/block (smem ~103KB -> 2 CTA/SM).
// ---------------------------------------------------------------------------
#define WS_STRIDE 136
#define XS_STRIDE 132
static const size_t GEMM_SMEM = (size_t)(128*WS_STRIDE + 64*XS_STRIDE) * 4;

__device__ __forceinline__ uint32_t f2tf32(float x) {
    uint32_t r;
    asm("cvt.rna.tf32.f32 %0, %1;" : "=r"(r) : "f"(x));
    return r;
}

__global__ void __launch_bounds__(256)
k_gemm_tc(const float* __restrict__ X, const float* __restrict__ W,
          const float* __restrict__ bias, int do_relu, int out_half,
          void* __restrict__ Hout, int n)
{
    extern __shared__ float sm[];
    float* Ws = sm;                  // [128][WS_STRIDE]
    float* Xs = sm + 128*WS_STRIDE;  // [64][XS_STRIDE]
    int tid = threadIdx.x;
    int row0 = blockIdx.x * 64;

    #pragma unroll 4
    for (int it = 0; it < 16; it++) {
        int idx = it*256 + tid;
        int k = idx >> 5, c4 = (idx & 31) << 2;
        float4 v = *(const float4*)(W + k*128 + c4);
        float4 t;
        t.x = __uint_as_float(f2tf32(v.x));
        t.y = __uint_as_float(f2tf32(v.y));
        t.z = __uint_as_float(f2tf32(v.z));
        t.w = __uint_as_float(f2tf32(v.w));
        *(float4*)(Ws + k*WS_STRIDE + c4) = t;
    }
    #pragma unroll 4
    for (int it = 0; it < 8; it++) {
        int idx = it*256 + tid;
        int r = idx >> 5, c4 = (idx & 31) << 2;
        float4 v = (row0 + r < n) ? *(const float4*)(X + (size_t)(row0+r)*128 + c4)
                                  : make_float4(0.f,0.f,0.f,0.f);
        float4 t;
        t.x = __uint_as_float(f2tf32(v.x));
        t.y = __uint_as_float(f2tf32(v.y));
        t.z = __uint_as_float(f2tf32(v.z));
        t.w = __uint_as_float(f2tf32(v.w));
        *(float4*)(Xs + r*XS_STRIDE + c4) = t;
    }
    __syncthreads();

    int w = tid >> 5, lane = tid & 31;
    int wr = w >> 1, wc = w & 1;      // rows 16*wr, cols 64*wc
    int g = lane >> 2, q = lane & 3;

    float acc[8][4];
    #pragma unroll
    for (int nt = 0; nt < 8; nt++)
        #pragma unroll
        for (int j = 0; j < 4; j++) acc[nt][j] = 0.f;

    #pragma unroll 4
    for (int kt = 0; kt < 16; kt++) {
        int kb = kt * 8;
        uint32_t a[4];
        {
            const float* p = Xs + (wr*16 + g)*XS_STRIDE + kb + q;
            a[0] = __float_as_uint(p[0]);
            a[1] = __float_as_uint(p[8*XS_STRIDE]);
            a[2] = __float_as_uint(p[4]);
            a[3] = __float_as_uint(p[8*XS_STRIDE + 4]);
        }
        #pragma unroll
        for (int nt = 0; nt < 8; nt++) {
            const float* p = Ws + (kb + q)*WS_STRIDE + wc*64 + nt*8 + g;
            uint32_t b0 = __float_as_uint(p[0]);
            uint32_t b1 = __float_as_uint(p[4*WS_STRIDE]);
            asm volatile(
                "mma.sync.aligned.m16n8k8.row.col.f32.tf32.tf32.f32 "
                "{%0,%1,%2,%3}, {%4,%5,%6,%7}, {%8,%9}, {%0,%1,%2,%3};"
                : "+f"(acc[nt][0]), "+f"(acc[nt][1]),
                  "+f"(acc[nt][2]), "+f"(acc[nt][3])
                : "r"(a[0]), "r"(a[1]), "r"(a[2]), "r"(a[3]),
                  "r"(b0), "r"(b1));
        }
    }

    int r0 = row0 + wr*16 + g;
    #pragma unroll
    for (int nt = 0; nt < 8; nt++) {
        int c = wc*64 + nt*8 + q*2;
        float2 v0 = make_float2(acc[nt][0], acc[nt][1]);
        float2 v1 = make_float2(acc[nt][2], acc[nt][3]);
        if (bias) {
            float b0 = bias[c], b1 = bias[c+1];
            v0.x += b0; v0.y += b1; v1.x += b0; v1.y += b1;
        }
        if (do_relu) {
            v0.x = fmaxf(v0.x,0.f); v0.y = fmaxf(v0.y,0.f);
            v1.x = fmaxf(v1.x,0.f); v1.y = fmaxf(v1.y,0.f);
        }
        if (out_half) {
            __half* H = (__half*)Hout;
            if (r0 < n)     *(__half2*)(H + (size_t)r0*128 + c)     = __floats2half2_rn(v0.x, v0.y);
            if (r0 + 8 < n) *(__half2*)(H + (size_t)(r0+8)*128 + c) = __floats2half2_rn(v1.x, v1.y);
        } else {
            float* H = (float*)Hout;
            if (r0 < n)     *(float2*)(H + (size_t)r0*128 + c)     = v0;
            if (r0 + 8 < n) *(float2*)(H + (size_t)(r0+8)*128 + c) = v1;
        }
    }
}

// ---------------------------------------------------------------------------
// Precompute all 12 relations' vs/vd = W @ a_{s,d}, one block each.
// ---------------------------------------------------------------------------
__global__ void k_wa_all(const float* __restrict__ c1W,
                         const float* __restrict__ c1as,
                         const float* __restrict__ c1ad,
                         const float* __restrict__ c2W,
                         const float* __restrict__ c2as,
                         const float* __restrict__ c2ad,
                         float* __restrict__ vmat)
{
    const int l2map[5] = {0,1,3,5,6};
    int b = blockIdx.x;
    int rel  = (b < 7) ? b : l2map[b-7];
    const float* W   = ((b < 7) ? c1W  : c2W ) + (size_t)rel*16384;
    const float* as_ = ((b < 7) ? c1as : c2as) + rel*128;
    const float* ad_ = ((b < 7) ? c1ad : c2ad) + rel*128;
    float* vs = vmat + (size_t)b*1024;
    float* vd = vs + 512;

    int k = threadIdx.x;
    #pragma unroll
    for (int h = 0; h < 4; h++) {
        float accs = 0.f, accd = 0.f;
        const float* Wr = W + (size_t)k*128 + h*32;
        const float* asr = as_ + h*32;
        const float* adr = ad_ + h*32;
        #pragma unroll
        for (int c = 0; c < 32; c++) {
            float wv = Wr[c];
            accs += wv * asr[c];
            accd += wv * adr[c];
        }
        vs[k*4 + h] = accs;
        vd[k*4 + h] = accd;
    }
}

// ---------------------------------------------------------------------------
// Multi-vector logits: al_j[row][h] = sum_k X[row][k] * v_j[k][h], j<nv.
// One read of X per row serves up to 6 logit vectors (warp per row).
// ---------------------------------------------------------------------------
struct AlxArgs { const float* v[6]; float* out[6]; };

__global__ void k_alx_multi(const float* __restrict__ X, AlxArgs A, int nv, int n)
{
    int g = blockIdx.x * blockDim.x + threadIdx.x;
    int row = g >> 5, lane = g & 31;
    if (row >= n) return;
    float4 x = *(const float4*)(X + (size_t)row*128 + lane*4);
    for (int j = 0; j < nv; j++) {
        const float4* v4 = (const float4*)A.v[j];
        float4 v0 = __ldg(v4 + lane*4 + 0);
        float4 v1 = __ldg(v4 + lane*4 + 1);
        float4 v2 = __ldg(v4 + lane*4 + 2);
        float4 v3 = __ldg(v4 + lane*4 + 3);
        float4 p;
        p.x = x.x*v0.x + x.y*v1.x + x.z*v2.x + x.w*v3.x;
        p.y = x.x*v0.y + x.y*v1.y + x.z*v2.y + x.w*v3.y;
        p.z = x.x*v0.z + x.y*v1.z + x.z*v2.z + x.w*v3.z;
        p.w = x.x*v0.w + x.y*v1.w + x.z*v2.w + x.w*v3.w;
        #pragma unroll
        for (int off = 16; off >= 1; off >>= 1) {
            p.x += __shfl_xor_sync(0xffffffffu, p.x, off);
            p.y += __shfl_xor_sync(0xffffffffu, p.y, off);
            p.z += __shfl_xor_sync(0xffffffffu, p.z, off);
            p.w += __shfl_xor_sync(0xffffffffu, p.w, off);
        }
        if (lane == 0) *(float4*)(A.out[j] + (size_t)row*4) = p;
    }
}

__global__ void k_initout(float* __restrict__ out, int n,
                          const float* __restrict__ b0,
                          const float* __restrict__ b1,
                          const float* __restrict__ b2)
{
    int i = blockIdx.x * blockDim.x + threadIdx.x;
    if (i >= n * 128) return;
    int c = i & 127;
    float v = b0[c] + b1[c];
    if (b2) v += b2[c];
    out[i] = v;
}

// ---------------------------------------------------------------------------
// CSR build: histogram, 3-kernel exclusive scan, scatter
// ---------------------------------------------------------------------------
__global__ void k_hist(const int* __restrict__ dst, int* __restrict__ cnt, int E)
{
    int i = blockIdx.x*blockDim.x + threadIdx.x;
    if (i < E) atomicAdd(cnt + dst[i], 1);
}

__global__ void k_scan_part(const int* __restrict__ cnt, int* __restrict__ part,
                            int* __restrict__ bsum, int n)
{
    __shared__ int smv[1024];
    int i = blockIdx.x*1024 + threadIdx.x;
    int x = (i < n) ? cnt[i] : 0;
    smv[threadIdx.x] = x; __syncthreads();
    #pragma unroll
    for (int off = 1; off < 1024; off <<= 1) {
        int v = (threadIdx.x >= off) ? smv[threadIdx.x - off] : 0;
        __syncthreads();
        smv[threadIdx.x] += v;
        __syncthreads();
    }
    if (i < n) part[i] = smv[threadIdx.x] - x;
    if (threadIdx.x == 1023) bsum[blockIdx.x] = smv[1023];
}

__global__ void k_scan_top(int* __restrict__ bsum, int nb)
{
    __shared__ int smv[1024];
    int x = (threadIdx.x < nb) ? bsum[threadIdx.x] : 0;
    smv[threadIdx.x] = x; __syncthreads();
    #pragma unroll
    for (int off = 1; off < 1024; off <<= 1) {
        int v = (threadIdx.x >= off) ? smv[threadIdx.x - off] : 0;
        __syncthreads();
        smv[threadIdx.x] += v;
        __syncthreads();
    }
    if (threadIdx.x < nb) bsum[threadIdx.x] = smv[threadIdx.x] - x;
}

__global__ void k_scan_add(const int* __restrict__ part, const int* __restrict__ bsum,
                           int* __restrict__ rowptr, int* __restrict__ cursor, int n)
{
    int i = blockIdx.x*1024 + threadIdx.x;
    if (i < n) {
        int v = part[i] + bsum[blockIdx.x];
        rowptr[i] = v;
        cursor[i] = v;
    }
}

__global__ void k_scatter(const int* __restrict__ src, const int* __restrict__ dst,
                          int* __restrict__ cursor, int* __restrict__ srt, int E)
{
    int i = blockIdx.x*blockDim.x + threadIdx.x;
    if (i < E) {
        int p = atomicAdd(cursor + dst[i], 1);
        srt[p] = src[i];
    }
}

// ---------------------------------------------------------------------------
// CSR GAT aggregation: warp per dst row, SINGLE fused pass over the segment:
// den and acc accumulated together; one red.v4 per row.
// ---------------------------------------------------------------------------
__global__ void k_gat_csr(const int* __restrict__ rowptr, const int* __restrict__ cnt,
                          const int* __restrict__ srt,
                          const float* __restrict__ alS, const float* __restrict__ alD,
                          const __half* __restrict__ Hs, float* __restrict__ out, int nd)
{
    int g = blockIdx.x*blockDim.x + threadIdx.x;
    int row = g >> 5, lane = g & 31;
    if (row >= nd) return;
    int m = __ldg(cnt + row);
    if (m == 0) return;
    int start = __ldg(rowptr + row);
    int h = lane >> 3;
    float adh = __ldg(alD + (size_t)row*4 + h);

    float den = 0.f;
    float4 acc = make_float4(0.f,0.f,0.f,0.f);
    for (int i = 0; i < m; i++) {
        int s = __ldg(srt + start + i);
        float e = __ldg(alS + (size_t)s*4 + h) + adh;
        if (e < 0.f) e *= 0.2f;
        float ex = __expf(e);
        den += ex;
        const __half2* hp = (const __half2*)(Hs + (size_t)s*128) + lane*2;
        float2 f01 = __half22float2(hp[0]);
        float2 f23 = __half22float2(hp[1]);
        acc.x += ex*f01.x; acc.y += ex*f01.y;
        acc.z += ex*f23.x; acc.w += ex*f23.y;
    }
    float inv = 1.f/(den + 1e-16f);
    float* o = out + (size_t)row*128 + lane*4;
    asm volatile("red.global.add.v4.f32 [%0], {%1, %2, %3, %4};"
                 :: "l"(__cvta_generic_to_global(o)),
                    "f"(acc.x*inv), "f"(acc.y*inv),
                    "f"(acc.z*inv), "f"(acc.w*inv)
                 : "memory");
}

__global__ void k_elu(float* __restrict__ x, int cnt)
{
    int i = blockIdx.x * blockDim.x + threadIdx.x;
    if (i >= cnt) return;
    float v = x[i];
    x[i] = (v > 0.f) ? v : (__expf(v) - 1.f);
}

__global__ void k_norm(const float* __restrict__ H, float* __restrict__ out, int n)
{
    int g = blockIdx.x * blockDim.x + threadIdx.x;
    int row = g >> 5, lane = g & 31;
    if (row >= n) return;
    float4 v = *(const float4*)(H + (size_t)row*128 + lane*4);
    float ss = v.x*v.x + v.y*v.y + v.z*v.z + v.w*v.w;
    #pragma unroll
    for (int off = 16; off >= 1; off >>= 1)
        ss += __shfl_xor_sync(0xffffffffu, ss, off);
    float s = 1.f / fmaxf(sqrtf(ss), 1e-12f);
    v.x *= s; v.y *= s; v.z *= s; v.w *= s;
    *(float4*)(out + (size_t)row*128 + lane*4) = v;
}

// ---------------------------------------------------------------------------
// host orchestration
// ---------------------------------------------------------------------------
struct Scratch {
    float *xp, *ou, *op, *ov, *xu2, *xp2, *hs, *hd, *albuf, *vmat;
    __half *hsh;
    int *cnt, *rowptr, *cursor, *part, *bsum, *srt;
};
struct DirInfo { int cbase; int ebase; int nd; };

static void build_csr(const int* src, const int* dst, int E, int nd,
                      int diri, const DirInfo& D, const Scratch& S)
{
    cudaMemsetAsync(S.cnt + D.cbase, 0, (size_t)nd*sizeof(int));
    k_hist<<<CDIV(E,256),256>>>(dst, S.cnt + D.cbase, E);
    int nb = CDIV(nd, 1024);
    k_scan_part<<<nb,1024>>>(S.cnt + D.cbase, S.part + D.cbase, S.bsum + diri*256, nd);
    k_scan_top<<<1,1024>>>(S.bsum + diri*256, nb);
    k_scan_add<<<nb,1024>>>(S.part + D.cbase, S.bsum + diri*256,
                            S.rowptr + D.cbase, S.cursor + D.cbase, nd);
    k_scatter<<<CDIV(E,256),256>>>(src, dst, S.cursor + D.cbase, S.srt + D.ebase, E);
}

// slot pointer into the logit buffer
static inline float* alslot(const Scratch& S, int slot)
{ return S.albuf + (size_t)slot * MAX_NU * 4; }

// One GAT relation aggregation (logits precomputed into slots).
static void do_rel(const float* xs, int ns,
                   const DirInfo& D, const float* W,
                   const float* alS, const float* alD,
                   float* out, const Scratch& S, bool gemm_done)
{
    if (!gemm_done)
        k_gemm_tc<<<CDIV(ns,64),256,GEMM_SMEM>>>(xs, W, nullptr, 0, 1, S.hsh, ns);
    k_gat_csr<<<CDIV(D.nd*32,256),256>>>(S.rowptr + D.cbase, S.cnt + D.cbase,
                                         S.srt + D.ebase, alS, alD,
                                         S.hsh, out, D.nd);
}

// launch k_alx_multi for one node type with vmat indices (+role) per slot
static void alx_multi(const float* X, int n, const Scratch& S,
                      const int* vmidx, const int* role, const int* slots, int nv)
{
    AlxArgs A;
    for (int j = 0; j < nv; j++) {
        A.v[j]   = S.vmat + (size_t)vmidx[j]*1024 + role[j]*512;
        A.out[j] = alslot(S, slots[j]);
    }
    for (int j = nv; j < 6; j++) { A.v[j] = nullptr; A.out[j] = nullptr; }
    k_alx_multi<<<CDIV(n*32,256),256>>>(X, A, nv, n);
}

extern "C" void kernel_launch(void* const* d_in, const int* in_sizes, int n_in,
                              void* d_out, int out_size)
{
    const int*   pt_id   = (const int*)  d_in[0];
    const float* x_num   = (const float*)d_in[1];
    const int*   e_up    = (const int*)  d_in[2];
    const int*   e_pv    = (const int*)  d_in[3];
    const int*   e_uv    = (const int*)  d_in[4];
    const int*   e_pp    = (const int*)  d_in[5];
    const float* user_e  = (const float*)d_in[6];
    const float* prod_e  = (const float*)d_in[7];
    const float* veh_e   = (const float*)d_in[8];
    const float* pt_emb  = (const float*)d_in[9];
    const float* fmlp_W  = (const float*)d_in[10];
    const float* fmlp_b  = (const float*)d_in[11];
    const float* c1W     = (const float*)d_in[12];
    const float* c1as    = (const float*)d_in[13];
    const float* c1ad    = (const float*)d_in[14];
    const float* c1b     = (const float*)d_in[15];
    const float* c2W     = (const float*)d_in[16];
    const float* c2as    = (const float*)d_in[17];
    const float* c2ad    = (const float*)d_in[18];
    const float* c2b     = (const float*)d_in[19];
    const float* upW1    = (const float*)d_in[20];
    const float* upb1    = (const float*)d_in[21];
    const float* upW2    = (const float*)d_in[22];
    const float* upb2    = (const float*)d_in[23];
    const float* ppW1    = (const float*)d_in[24];
    const float* ppb1    = (const float*)d_in[25];
    const float* ppW2    = (const float*)d_in[26];
    const float* ppb2    = (const float*)d_in[27];

    const int NPR = in_sizes[0];
    const int NU  = in_sizes[6] / 128;
    const int NV  = in_sizes[8] / 128;
    const int EUP = in_sizes[2] / 2;
    const int EPV = in_sizes[3] / 2;
    const int EUV = in_sizes[4] / 2;
    const int EPP = in_sizes[5] / 2;

    Scratch S;
    cudaGetSymbolAddress((void**)&S.xp , g_xp);
    cudaGetSymbolAddress((void**)&S.ou , g_ou);
    cudaGetSymbolAddress((void**)&S.op , g_op);
    cudaGetSymbolAddress((void**)&S.ov , g_ov);
    cudaGetSymbolAddress((void**)&S.xu2, g_xu2);
    cudaGetSymbolAddress((void**)&S.xp2, g_xp2);
    cudaGetSymbolAddress((void**)&S.hs , g_hs);
    cudaGetSymbolAddress((void**)&S.hd , g_hd);
    cudaGetSymbolAddress((void**)&S.hsh, g_hsh);
    cudaGetSymbolAddress((void**)&S.albuf, g_albuf);
    cudaGetSymbolAddress((void**)&S.vmat, g_vmat);
    cudaGetSymbolAddress((void**)&S.cnt, g_cnt);
    cudaGetSymbolAddress((void**)&S.rowptr, g_rowptr);
    cudaGetSymbolAddress((void**)&S.cursor, g_cursor);
    cudaGetSymbolAddress((void**)&S.part, g_part);
    cudaGetSymbolAddress((void**)&S.bsum, g_bsum);
    cudaGetSymbolAddress((void**)&S.srt, g_srt);

    cudaFuncSetAttribute(k_gemm_tc, cudaFuncAttributeMaxDynamicSharedMemorySize,
                         (int)GEMM_SMEM);

    const int *up0 = e_up, *up1 = e_up + EUP;
    const int *pv0 = e_pv, *pv1 = e_pv + EPV;
    const int *uv0 = e_uv, *uv1 = e_uv + EUV;
    const int *pp0 = e_pp, *pp1 = e_pp + EPP;

    const int* dsrc[7] = {up0, up1, pv0, pv1, uv0, uv1, pp0};
    const int* ddst[7] = {up1, up0, pv1, pv0, uv1, uv0, pp1};
    int  dE [7] = {EUP, EUP, EPV, EPV, EUV, EUV, EPP};
    int  dND[7] = {NPR, NU,  NV,  NPR, NV,  NU,  NPR};
    DirInfo D[7];
    {
        int cb = 0, eb = 0;
        for (int d = 0; d < 7; d++) {
            D[d].cbase = cb; D[d].ebase = eb; D[d].nd = dND[d];
            cb += dND[d]; eb += dE[d];
        }
    }

    // ---- launch order: #3 is the big 200k-row GEMM (profiled by ncu -s 5).
    k_wa_all<<<12,128>>>(c1W, c1as, c1ad, c2W, c2as, c2ad, S.vmat);              // 0
    k_feat<<<CDIV(NPR*128,256),256>>>(pt_id, x_num, pt_emb, fmlp_W, fmlp_b,
                                      prod_e, S.xp, NPR);                        // 1
    k_initout<<<CDIV(NU*128,256),256>>>(S.ou, NU, c1b+1*128, c1b+5*128, nullptr);// 2
    k_gemm_tc<<<CDIV(NU,64),256,GEMM_SMEM>>>(user_e, c1W+0*16384, nullptr, 0, 1,
                                             S.hsh, NU);                         // 3 (profiled)
    k_initout<<<CDIV(NPR*128,256),256>>>(S.op, NPR, c1b+0*128, c1b+3*128, c1b+6*128);
    k_initout<<<CDIV(NV*128,256),256>>>(S.ov, NV, c1b+2*128, c1b+4*128, nullptr);

    for (int d = 0; d < 7; d++)
        build_csr(dsrc[d], ddst[d], dE[d], dND[d], d, D[d], S);

    // ---- layer 1: logit slots ---------------------------------------------
    // user  slots 0..3 : s(rel0), s(rel4), d(rel1), d(rel5)
    // prod  slots 4..9 : s(rel1), s(rel2), s(rel6), d(rel0), d(rel3), d(rel6)
    // veh   slots 10..13: s(rel3), s(rel5), d(rel2), d(rel4)
    {
        const int uvm[4] = {0,4,1,5},   urole[4] = {0,0,1,1},   uslot[4] = {0,1,2,3};
        const int pvm[6] = {1,2,6,0,3,6}, prole[6] = {0,0,0,1,1,1}, pslot[6] = {4,5,6,7,8,9};
        const int vvm[4] = {3,5,2,4},   vrole[4] = {0,0,1,1},   vslot[4] = {10,11,12,13};
        alx_multi(user_e, NU,  S, uvm, urole, uslot, 4);
        alx_multi(S.xp,   NPR, S, pvm, prole, pslot, 6);
        alx_multi(veh_e,  NV,  S, vvm, vrole, vslot, 4);
    }
    {
        const float *xu = user_e, *xp = S.xp, *xv = veh_e;
        do_rel(xu,NU,  D[0], c1W+0*16384, alslot(S,0),  alslot(S,7),  S.op, S, true);
        do_rel(xp,NPR, D[1], c1W+1*16384, alslot(S,4),  alslot(S,2),  S.ou, S, false);
        do_rel(xp,NPR, D[2], c1W+2*16384, alslot(S,5),  alslot(S,12), S.ov, S, false);
        do_rel(xv,NV,  D[3], c1W+3*16384, alslot(S,10), alslot(S,8),  S.op, S, false);
        do_rel(xu,NU,  D[4], c1W+4*16384, alslot(S,1),  alslot(S,13), S.ov, S, false);
        do_rel(xv,NV,  D[5], c1W+5*16384, alslot(S,11), alslot(S,3),  S.ou, S, false);
        do_rel(xp,NPR, D[6], c1W+6*16384, alslot(S,6),  alslot(S,9),  S.op, S, false);
    }
    k_elu<<<CDIV(NU*128,256),256>>>(S.ou, NU*128);
    k_elu<<<CDIV(NPR*128,256),256>>>(S.op, NPR*128);
    k_elu<<<CDIV(NV*128,256),256>>>(S.ov, NV*128);

    // ---- layer 2 (dst==vehicle relations pruned); vmat 7..11 = rels {0,1,3,5,6}
    k_initout<<<CDIV(NU*128,256),256>>>(S.xu2, NU, c2b+1*128, c2b+5*128, nullptr);
    k_initout<<<CDIV(NPR*128,256),256>>>(S.xp2, NPR, c2b+0*128, c2b+3*128, c2b+6*128);
    // user  slots 0..2 : s(rel0=vm7), d(rel1=vm8), d(rel5=vm10)
    // prod  slots 4..8 : s(rel1=vm8), s(rel6=vm11), d(rel0=vm7), d(rel3=vm9), d(rel6=vm11)
    // veh   slots 10..11: s(rel3=vm9), s(rel5=vm10)
    {
        const int uvm[3] = {7,8,10},  urole[3] = {0,1,1},  uslot[3] = {0,1,2};
        const int pvm[5] = {8,11,7,9,11}, prole[5] = {0,0,1,1,1}, pslot[5] = {4,5,6,7,8};
        const int vvm[2] = {9,10},    vrole[2] = {0,0},    vslot[2] = {10,11};
        alx_multi(S.ou, NU,  S, uvm, urole, uslot, 3);
        alx_multi(S.op, NPR, S, pvm, prole, pslot, 5);
        alx_multi(S.ov, NV,  S, vvm, vrole, vslot, 2);
    }
    {
        const float *xu = S.ou, *xp = S.op, *xv = S.ov;
        do_rel(xu,NU,  D[0], c2W+0*16384, alslot(S,0),  alslot(S,6), S.xp2, S, false);
        do_rel(xp,NPR, D[1], c2W+1*16384, alslot(S,4),  alslot(S,1), S.xu2, S, false);
        do_rel(xv,NV,  D[3], c2W+3*16384, alslot(S,10), alslot(S,7), S.xp2, S, false);
        do_rel(xv,NV,  D[5], c2W+5*16384, alslot(S,11), alslot(S,2), S.xu2, S, false);
        do_rel(xp,NPR, D[6], c2W+6*16384, alslot(S,5),  alslot(S,8), S.xp2, S, false);
    }
    k_elu<<<CDIV(NU*128,256),256>>>(S.xu2, NU*128);
    k_elu<<<CDIV(NPR*128,256),256>>>(S.xp2, NPR*128);

    // ---- projections + L2 norm (fp32 path) --------------------------------
    float* out = (float*)d_out;
    k_gemm_tc<<<CDIV(NU,64),256,GEMM_SMEM>>>(S.xu2, upW1, upb1, 1, 0, S.hs, NU);
    k_gemm_tc<<<CDIV(NU,64),256,GEMM_SMEM>>>(S.hs, upW2, upb2, 0, 0, S.hd, NU);
    k_norm<<<CDIV(NU*32,256),256>>>(S.hd, out, NU);
    k_gemm_tc<<<CDIV(NPR,64),256,GEMM_SMEM>>>(S.xp2, ppW1, ppb1, 1, 0, S.hs, NPR);
    k_gemm_tc<<<CDIV(NPR,64),256,GEMM_SMEM>>>(S.hs, ppW2, ppb2, 0, 0, S.hd, NPR);
    k_norm<<<CDIV(NPR*32,256),256>>>(S.hd, out + (size_t)NU*128, NPR);
}